// round 3
// baseline (speedup 1.0000x reference)
#include <cuda_runtime.h>

#define KE_HALF 7.199822675975274f   /* KE/2 */
#define LOG2E   1.4426950408889634f
#define MAX_NODES 131072

// Scratch (no cudaMalloc allowed): per-node (z, z^p * d) table + derived params.
__device__ float2 g_node[MAX_NODES];
__device__ float  g_par[8];   // [0..3] = -a_k*log2(e), [4..7] = normalized c_k

__device__ __forceinline__ float softplus_f(float x) {
    return fmaxf(x, 0.0f) + log1pf(__expf(-fabsf(x)));
}

__device__ __forceinline__ float ex2f(float x) {
    float y; asm("ex2.approx.ftz.f32 %0, %1;" : "=f"(y) : "f"(x)); return y;
}

__device__ __forceinline__ float4 ldcs4(const float4* p) {
    float4 v;
    asm("ld.global.cs.v4.f32 {%0,%1,%2,%3}, [%4];"
        : "=f"(v.x), "=f"(v.y), "=f"(v.z), "=f"(v.w) : "l"(p));
    return v;
}
__device__ __forceinline__ int4 ldcs4i(const int4* p) {
    int4 v;
    asm("ld.global.cs.v4.b32 {%0,%1,%2,%3}, [%4];"
        : "=r"(v.x), "=r"(v.y), "=r"(v.z), "=r"(v.w) : "l"(p));
    return v;
}

// Fused: zero output + per-node (z, z^p*d) precompute + (thread 0) param derivation.
__global__ void node_kernel(const float* __restrict__ z,
                            const float* __restrict__ p_raw,
                            const float* __restrict__ d_raw,
                            const float* __restrict__ a1, const float* __restrict__ a2,
                            const float* __restrict__ a3, const float* __restrict__ a4,
                            const float* __restrict__ c1, const float* __restrict__ c2,
                            const float* __restrict__ c3, const float* __restrict__ c4,
                            float* __restrict__ out, int n, int n_out) {
    int i = blockIdx.x * blockDim.x + threadIdx.x;
    if (i == 0) {
        float A1 = softplus_f(a1[0]), A2 = softplus_f(a2[0]);
        float A3 = softplus_f(a3[0]), A4 = softplus_f(a4[0]);
        float C1 = softplus_f(c1[0]), C2 = softplus_f(c2[0]);
        float C3 = softplus_f(c3[0]), C4 = softplus_f(c4[0]);
        float s = 1.0f / (C1 + C2 + C3 + C4);
        g_par[0] = -A1 * LOG2E; g_par[1] = -A2 * LOG2E;
        g_par[2] = -A3 * LOG2E; g_par[3] = -A4 * LOG2E;
        g_par[4] = C1 * s; g_par[5] = C2 * s; g_par[6] = C3 * s; g_par[7] = C4 * s;
    }
    if (i < n_out) out[i] = 0.0f;
    if (i < n) {
        float p = softplus_f(p_raw[0]);
        float d = softplus_f(d_raw[0]);
        float zi = z[i];
        g_node[i] = make_float2(zi, __powf(zi, p) * d);
    }
}

__global__ void __launch_bounds__(256, 8)
edge_kernel(const float* __restrict__ cut, const float* __restrict__ len,
            const int* __restrict__ snd, const int* __restrict__ rcv,
            float* __restrict__ out, int E) {
    int i4 = blockIdx.x * blockDim.x + threadIdx.x;
    long long base = (long long)i4 * 4;
    if (base >= E) return;

    float4 Lv, Cv; int4 Sv, Rv;
    if (base + 3 < E) {
        Lv = ldcs4(reinterpret_cast<const float4*>(len + base));
        Cv = ldcs4(reinterpret_cast<const float4*>(cut + base));
        Sv = ldcs4i(reinterpret_cast<const int4*>(snd + base));
        Rv = ldcs4i(reinterpret_cast<const int4*>(rcv + base));
    } else {
        float* lp = &Lv.x; float* cp = &Cv.x; int* sp = &Sv.x; int* rp = &Rv.x;
        for (int k = 0; k < 4; k++) {
            long long e = base + k;
            lp[k] = (e < E) ? len[e] : 2.0f;   // L >= 1.5 -> w == 0 -> no-op
            cp[k] = (e < E) ? cut[e] : 0.0f;
            sp[k] = (e < E) ? snd[e] : 0;
            rp[k] = (e < E) ? rcv[e] : 0;
        }
    }

    const float b1 = g_par[0], b2 = g_par[1], b3 = g_par[2], b4 = g_par[3];
    const float c1 = g_par[4], c2 = g_par[5], c3 = g_par[6], c4 = g_par[7];

    const float* lp = &Lv.x; const float* cp = &Cv.x;
    const int* sp = &Sv.x; const int* rp = &Rv.x;

#pragma unroll
    for (int k = 0; k < 4; k++) {
        float L = lp[k];
        float cc = L * (1.0f / 1.5f);          // switch argument, x_on=0, x_off=1.5
        if (cc >= 1.0f) continue;              // w == 0 exactly: ~60% of edges skipped

        // w = 1/(1 + exp(f)),  f = 1/(1-cc) - 1/cc = (2cc-1)/(cc(1-cc))
        // e^f computed as ex2(f * log2e); fold w's denominator into the 1/L divide:
        //   w * x = KE*cut*zi*zj / ((1 + e^f) * L)
        float om = 1.0f - cc;
        float fl = __fdividef((cc + cc - 1.0f) * LOG2E, cc * om);
        float ef = ex2f(fl);
        float D  = (1.0f + ef) * fmaxf(L, 1e-6f);

        int s = sp[k], r = rp[k];
        float2 nj = g_node[s];                 // (z_j, z_j^p * d)
        float2 ni = g_node[r];                 // (z_i, z_i^p * d)

        float num = KE_HALF * cp[k] * ni.x * nj.x;
        float t = L * (ni.y + nj.y);           // rzd
        float y = c1 * ex2f(b1 * t) + c2 * ex2f(b2 * t)
                + c3 * ex2f(b3 * t) + c4 * ex2f(b4 * t);

        atomicAdd(out + r, __fdividef(num * y, D));
    }
}

extern "C" void kernel_launch(void* const* d_in, const int* in_sizes, int n_in,
                              void* d_out, int out_size) {
    const float* z   = (const float*)d_in[0];
    const float* cut = (const float*)d_in[1];
    const int*   snd = (const int*)  d_in[2];
    const int*   rcv = (const int*)  d_in[3];
    const float* len = (const float*)d_in[4];

    int pb = n_in - 10;
    const float* a1 = (const float*)d_in[pb + 0];
    const float* a2 = (const float*)d_in[pb + 1];
    const float* a3 = (const float*)d_in[pb + 2];
    const float* a4 = (const float*)d_in[pb + 3];
    const float* c1 = (const float*)d_in[pb + 4];
    const float* c2 = (const float*)d_in[pb + 5];
    const float* c3 = (const float*)d_in[pb + 6];
    const float* c4 = (const float*)d_in[pb + 7];
    const float* pr = (const float*)d_in[pb + 8];
    const float* dr = (const float*)d_in[pb + 9];

    int N = in_sizes[0];
    int E = in_sizes[2];
    if (N > MAX_NODES) N = MAX_NODES;

    float* out = (float*)d_out;

    int cover = (N > out_size) ? N : out_size;
    node_kernel<<<(cover + 255) / 256, 256>>>(z, pr, dr, a1, a2, a3, a4,
                                              c1, c2, c3, c4, out, N, out_size);

    int n4 = (E + 3) / 4;
    edge_kernel<<<(n4 + 255) / 256, 256>>>(cut, len, snd, rcv, out, E);
}